// round 1
// baseline (speedup 1.0000x reference)
#include <cuda_runtime.h>
#include <cuda_bf16.h>
#include <cstdint>

// Problem shape (fixed by the reference)
constexpr int Bc = 2;
constexpr int Lc = 4096;
constexpr int DK = 128;
constexpr int DV = 128;
constexpr int C  = 64;           // chunk length
constexpr int NC = Lc / C;       // 64 chunks per batch
constexpr int TC = Bc * NC;      // 128 total chunks
constexpr float EPS = 1e-6f;

// Scratch (device globals; no runtime allocation allowed)
__device__ float g_kv   [(size_t)TC * DK * DV];  // per-chunk phiK^T V   (8 MB)
__device__ float g_kvpre[(size_t)TC * DK * DV];  // exclusive prefix     (8 MB)
__device__ float g_ks   [(size_t)TC * DK];       // per-chunk sum phiK
__device__ float g_kspre[(size_t)TC * DK];       // exclusive prefix

__device__ __forceinline__ float phi(float x) {
    // elu(x)+1 : x>0 -> x+1 ; else exp(x)
    return x > 0.f ? x + 1.f : __expf(x);
}

// ---------------------------------------------------------------------------
// Kernel 1: per-chunk KV = phiK^T @ V  (DKxDV), Ksum = sum_l phiK
// grid = TC blocks, 256 threads. smem = C*DK + C*DV floats (64 KB)
// ---------------------------------------------------------------------------
__global__ void __launch_bounds__(256, 1)
k_chunk_kv(const float* __restrict__ K, const float* __restrict__ V) {
    extern __shared__ float sm[];
    float* sK = sm;             // [C][DK] natural (l-major)
    float* sV = sm + C * DK;    // [C][DV]

    const int bc = blockIdx.x;            // b*NC + c
    const int b  = bc / NC;
    const int c  = bc % NC;
    const int l0 = c * C;
    const int tid = threadIdx.x;

    for (int e = tid; e < C * DK; e += 256) {
        const int i = e >> 7;       // row in chunk
        const int k = e & 127;      // feature
        const size_t g = ((size_t)(b * Lc + l0 + i)) * DK + k;
        sK[e] = phi(K[g]);
        sV[e] = V[g];               // DV == DK so same flat index works
    }
    __syncthreads();

    const int ty = tid >> 4, tx = tid & 15;
    const int k0 = ty * 8, v0 = tx * 8;

    float acc[8][8];
#pragma unroll
    for (int r = 0; r < 8; r++)
#pragma unroll
        for (int s = 0; s < 8; s++) acc[r][s] = 0.f;

    for (int l = 0; l < C; l++) {
        float a[8], bb[8];
        float4 a0 = *(const float4*)&sK[l * DK + k0];
        float4 a1 = *(const float4*)&sK[l * DK + k0 + 4];
        a[0]=a0.x; a[1]=a0.y; a[2]=a0.z; a[3]=a0.w;
        a[4]=a1.x; a[5]=a1.y; a[6]=a1.z; a[7]=a1.w;
        float4 b0 = *(const float4*)&sV[l * DV + v0];
        float4 b1 = *(const float4*)&sV[l * DV + v0 + 4];
        bb[0]=b0.x; bb[1]=b0.y; bb[2]=b0.z; bb[3]=b0.w;
        bb[4]=b1.x; bb[5]=b1.y; bb[6]=b1.z; bb[7]=b1.w;
#pragma unroll
        for (int r = 0; r < 8; r++)
#pragma unroll
            for (int s = 0; s < 8; s++)
                acc[r][s] = fmaf(a[r], bb[s], acc[r][s]);
    }

    float* kvout = g_kv + (size_t)bc * DK * DV;
#pragma unroll
    for (int r = 0; r < 8; r++) {
        float4 o0 = make_float4(acc[r][0], acc[r][1], acc[r][2], acc[r][3]);
        float4 o1 = make_float4(acc[r][4], acc[r][5], acc[r][6], acc[r][7]);
        *(float4*)&kvout[(size_t)(k0 + r) * DV + v0]     = o0;
        *(float4*)&kvout[(size_t)(k0 + r) * DV + v0 + 4] = o1;
    }

    if (tid < DK) {
        float s = 0.f;
        for (int l = 0; l < C; l++) s += sK[l * DK + tid];
        g_ks[(size_t)bc * DK + tid] = s;
    }
}

// ---------------------------------------------------------------------------
// Kernel 2: exclusive prefix scan over chunks (per batch)
// grid = Bc*DK blocks, DV threads
// ---------------------------------------------------------------------------
__global__ void __launch_bounds__(128, 8)
k_scan(void) {
    const int b = blockIdx.x / DK;
    const int k = blockIdx.x % DK;
    const int v = threadIdx.x;

    float run = 0.f;
    for (int c = 0; c < NC; c++) {
        const size_t idx = (((size_t)(b * NC + c) * DK) + k) * DV + v;
        g_kvpre[idx] = run;
        run += g_kv[idx];
    }
    if (v == 0) {
        float rs = 0.f;
        for (int c = 0; c < NC; c++) {
            const size_t idx = (size_t)(b * NC + c) * DK + k;
            g_kspre[idx] = rs;
            rs += g_ks[idx];
        }
    }
}

// ---------------------------------------------------------------------------
// Kernel 3: per chunk: A = mask(phiQ phiK^T); out = (A V + phiQ Spre) / Z
// Z_i = rowsum(A)_i + phiQ_i . Kspre
// grid = TC blocks, 256 threads. smem ~114 KB
// ---------------------------------------------------------------------------
constexpr int P  = C + 1;   // 65, padded transposed stride
constexpr int PA = C + 1;   // 65, sA row stride (stored [j][i])

__global__ void __launch_bounds__(256, 1)
k_output(const float* __restrict__ Q, const float* __restrict__ K,
         const float* __restrict__ V, float* __restrict__ out) {
    extern __shared__ float sm[];
    float* sQt = sm;                       // [DK][P]  phiQ transposed (k-major)
    float* sKt = sQt + DK * P;             // [DK][P]  phiK transposed
    float* sA  = sKt + DK * P;             // [C][PA]  A stored transposed [j][i]
    float* sV  = sA  + C * PA;             // [C][DV]  natural
    float* sKs = sV  + C * DV;             // [DK]
    float* sZ  = sKs + DK;                 // [C]

    const int bc = blockIdx.x;
    const int b  = bc / NC;
    const int c  = bc % NC;
    const int l0 = c * C;
    const int tid = threadIdx.x;

    for (int e = tid; e < C * DK; e += 256) {
        const int i = e >> 7;
        const int k = e & 127;
        const size_t g = ((size_t)(b * Lc + l0 + i)) * DK + k;
        sQt[k * P + i] = phi(Q[g]);
        sKt[k * P + i] = phi(K[g]);
        sV[e] = V[g];
    }
    if (tid < DK) sKs[tid] = g_kspre[(size_t)bc * DK + tid];
    __syncthreads();

    const int ty = tid >> 4, tx = tid & 15;
    const int i0 = ty * 4;     // 16*4 = 64 rows
    const int j0 = tx * 4;     // 16*4 = 64 cols (phase 1)
    const int v0 = tx * 8;     // 16*8 = 128 cols (phase 2)

    // ---- phase 1: A[i][j] = sum_k phiQ[i][k] phiK[j][k], masked i>=j ----
    {
        float accA[4][4];
#pragma unroll
        for (int r = 0; r < 4; r++)
#pragma unroll
            for (int s = 0; s < 4; s++) accA[r][s] = 0.f;

        for (int k = 0; k < DK; k++) {
            float af[4], bf[4];
#pragma unroll
            for (int r = 0; r < 4; r++) af[r] = sQt[k * P + i0 + r];
#pragma unroll
            for (int s = 0; s < 4; s++) bf[s] = sKt[k * P + j0 + s];
#pragma unroll
            for (int r = 0; r < 4; r++)
#pragma unroll
                for (int s = 0; s < 4; s++)
                    accA[r][s] = fmaf(af[r], bf[s], accA[r][s]);
        }
#pragma unroll
        for (int s = 0; s < 4; s++)
#pragma unroll
            for (int r = 0; r < 4; r++) {
                const int i = i0 + r, j = j0 + s;
                sA[j * PA + i] = (i >= j) ? accA[r][s] : 0.f;
            }
    }
    __syncthreads();

    // ---- Z: rowsum of masked A  + phiQ . Kspre ----
    if (tid < C) {
        const int i = tid;
        float z = 0.f;
        for (int j = 0; j < C; j++) z += sA[j * PA + i];
        for (int k = 0; k < DK; k++) z += sQt[k * P + i] * sKs[k];
        sZ[i] = z;
    }
    __syncthreads();

    // ---- phase 2: out = A @ V + phiQ @ Spre ----
    float acc[4][8];
#pragma unroll
    for (int r = 0; r < 4; r++)
#pragma unroll
        for (int s = 0; s < 8; s++) acc[r][s] = 0.f;

    // intra-chunk: loop over j
    for (int j = 0; j < C; j++) {
        float af[4];
#pragma unroll
        for (int r = 0; r < 4; r++) af[r] = sA[j * PA + i0 + r];
        float4 b0 = *(const float4*)&sV[j * DV + v0];
        float4 b1 = *(const float4*)&sV[j * DV + v0 + 4];
        float bb[8] = {b0.x, b0.y, b0.z, b0.w, b1.x, b1.y, b1.z, b1.w};
#pragma unroll
        for (int r = 0; r < 4; r++)
#pragma unroll
            for (int s = 0; s < 8; s++)
                acc[r][s] = fmaf(af[r], bb[s], acc[r][s]);
    }

    // inter-chunk: loop over k, streaming Spre from global (L1-resident per block)
    const float* Sp = g_kvpre + (size_t)bc * DK * DV;
    for (int k = 0; k < DK; k++) {
        float af[4];
#pragma unroll
        for (int r = 0; r < 4; r++) af[r] = sQt[k * P + i0 + r];
        float4 b0 = __ldg((const float4*)&Sp[(size_t)k * DV + v0]);
        float4 b1 = __ldg((const float4*)&Sp[(size_t)k * DV + v0 + 4]);
        float bb[8] = {b0.x, b0.y, b0.z, b0.w, b1.x, b1.y, b1.z, b1.w};
#pragma unroll
        for (int r = 0; r < 4; r++)
#pragma unroll
            for (int s = 0; s < 8; s++)
                acc[r][s] = fmaf(af[r], bb[s], acc[r][s]);
    }

    // epilogue: divide by Z and store
#pragma unroll
    for (int r = 0; r < 4; r++) {
        const float invz = 1.f / (sZ[i0 + r] + EPS);
        float4 o0 = make_float4(acc[r][0]*invz, acc[r][1]*invz,
                                acc[r][2]*invz, acc[r][3]*invz);
        float4 o1 = make_float4(acc[r][4]*invz, acc[r][5]*invz,
                                acc[r][6]*invz, acc[r][7]*invz);
        const size_t g = ((size_t)(b * Lc + l0 + i0 + r)) * DV + v0;
        *(float4*)&out[g]     = o0;
        *(float4*)&out[g + 4] = o1;
    }
}

// ---------------------------------------------------------------------------
extern "C" void kernel_launch(void* const* d_in, const int* in_sizes, int n_in,
                              void* d_out, int out_size) {
    const float* Q = (const float*)d_in[0];
    const float* K = (const float*)d_in[1];
    const float* V = (const float*)d_in[2];
    float* out = (float*)d_out;

    const int smem1 = (C * DK + C * DV) * (int)sizeof(float);                 // 64 KB
    const int smem3 = (DK * P + DK * P + C * PA + C * DV + DK + C)
                      * (int)sizeof(float);                                   // ~114 KB

    cudaFuncSetAttribute(k_chunk_kv, cudaFuncAttributeMaxDynamicSharedMemorySize, smem1);
    cudaFuncSetAttribute(k_output,  cudaFuncAttributeMaxDynamicSharedMemorySize, smem3);

    k_chunk_kv<<<TC, 256, smem1>>>(K, V);
    k_scan<<<Bc * DK, 128>>>();
    k_output<<<TC, 256, smem3>>>(Q, K, V, out);
}

// round 2
// speedup vs baseline: 1.4779x; 1.4779x over previous
#include <cuda_runtime.h>
#include <cuda_bf16.h>
#include <cstdint>

typedef unsigned long long u64;

// Problem shape (fixed by the reference)
constexpr int Bc = 2;
constexpr int Lc = 4096;
constexpr int DK = 128;
constexpr int DV = 128;
constexpr int C  = 64;           // chunk length
constexpr int NC = Lc / C;       // 64 chunks per batch
constexpr int TC = Bc * NC;      // 128 total chunks
constexpr float EPS = 1e-6f;

constexpr int PT = 66;           // padded stride for transposed phiQ/phiK (even -> v2 loads)
constexpr int PA = 66;           // padded stride for A (stored [j][i], even)

// Scratch (device globals; no runtime allocation allowed)
__device__ float g_kv   [(size_t)TC * DK * DV];  // per-chunk phiK^T V   (8 MB)
__device__ float g_kvpre[(size_t)TC * DK * DV];  // exclusive prefix     (8 MB)
__device__ float g_ks   [(size_t)TC * DK];       // per-chunk sum phiK
__device__ float g_kspre[(size_t)TC * DK];       // exclusive prefix

__device__ __forceinline__ float phi(float x) {
    return x > 0.f ? x + 1.f : __expf(x);   // elu(x)+1
}

// ---- packed f32x2 helpers ------------------------------------------------
__device__ __forceinline__ u64 pk(float lo, float hi) {
    u64 r; asm("mov.b64 %0, {%1, %2};" : "=l"(r) : "f"(lo), "f"(hi)); return r;
}
__device__ __forceinline__ void fma2(u64& d, u64 a, u64 b) {
    asm("fma.rn.f32x2 %0, %1, %2, %0;" : "+l"(d) : "l"(a), "l"(b));
}
__device__ __forceinline__ float2 up(u64 v) {
    float2 f; asm("mov.b64 {%0, %1}, %2;" : "=f"(f.x), "=f"(f.y) : "l"(v)); return f;
}

// ---------------------------------------------------------------------------
// Kernel 1: per-chunk KV = phiK^T @ V  (DKxDV), Ksum = sum_l phiK
// grid = TC, 512 threads. smem = 64 KB
// ---------------------------------------------------------------------------
__global__ void __launch_bounds__(512, 1)
k_chunk_kv(const float* __restrict__ K, const float* __restrict__ V) {
    extern __shared__ float sm[];
    float* sK = sm;             // [C][DK]
    float* sV = sm + C * DK;    // [C][DV]

    const int bc = blockIdx.x;
    const int b  = bc / NC;
    const int c  = bc % NC;
    const int l0 = c * C;
    const int tid = threadIdx.x;

    for (int e = tid; e < C * DK; e += 512) {
        const int i = e >> 7, k = e & 127;
        const size_t g = ((size_t)(b * Lc + l0 + i)) * DK + k;
        sK[e] = phi(K[g]);
        sV[e] = V[g];
    }
    __syncthreads();

    const int ty = tid >> 5, tx = tid & 31;   // ty = warp id (uniform a-reads)
    const int k0 = ty * 8, v0 = tx * 4;

    u64 acc[4][4];   // [k-pair][v] : {KV[k0+2rp][v0+s], KV[k0+2rp+1][v0+s]}
#pragma unroll
    for (int r = 0; r < 4; r++)
#pragma unroll
        for (int s = 0; s < 4; s++) acc[r][s] = 0ull;

#pragma unroll 4
    for (int l = 0; l < C; l++) {
        float4 a0 = *(const float4*)&sK[l * DK + k0];
        float4 a1 = *(const float4*)&sK[l * DK + k0 + 4];
        float4 bv = *(const float4*)&sV[l * DV + v0];
        u64 ap[4] = { pk(a0.x, a0.y), pk(a0.z, a0.w), pk(a1.x, a1.y), pk(a1.z, a1.w) };
        u64 br[4] = { pk(bv.x, bv.x), pk(bv.y, bv.y), pk(bv.z, bv.z), pk(bv.w, bv.w) };
#pragma unroll
        for (int r = 0; r < 4; r++)
#pragma unroll
            for (int s = 0; s < 4; s++)
                fma2(acc[r][s], ap[r], br[s]);
    }

    float* kvout = g_kv + (size_t)bc * DK * DV;
#pragma unroll
    for (int r = 0; r < 4; r++) {
        float2 e0 = up(acc[r][0]), e1 = up(acc[r][1]);
        float2 e2 = up(acc[r][2]), e3 = up(acc[r][3]);
        *(float4*)&kvout[(size_t)(k0 + 2*r    ) * DV + v0] = make_float4(e0.x, e1.x, e2.x, e3.x);
        *(float4*)&kvout[(size_t)(k0 + 2*r + 1) * DV + v0] = make_float4(e0.y, e1.y, e2.y, e3.y);
    }

    if (tid < DK) {                    // sK read-only since sync; no extra barrier
        float s = 0.f;
#pragma unroll 8
        for (int l = 0; l < C; l++) s += sK[l * DK + tid];
        g_ks[(size_t)bc * DK + tid] = s;
    }
}

// ---------------------------------------------------------------------------
// Kernel 2: exclusive prefix over chunks, float4-vectorized (L2-resident)
// grid = 128 blocks x 64 threads  (8192 threads = Bc*DK*DV/4)
// ---------------------------------------------------------------------------
__global__ void __launch_bounds__(64, 8)
k_scan(void) {
    const int gid = blockIdx.x * 64 + threadIdx.x;
    const int b  = gid >> 12;
    const int k  = (gid >> 5) & 127;
    const int v4 = (gid & 31) * 4;

    const size_t base = (((size_t)(b * NC)) * DK + k) * DV + v4;
    const size_t cstr = (size_t)DK * DV;

    float4 run = make_float4(0.f, 0.f, 0.f, 0.f);
#pragma unroll 1
    for (int c = 0; c < NC; c += 4) {
        float4 x0 = *(const float4*)(g_kv + base + (size_t)(c + 0) * cstr);
        float4 x1 = *(const float4*)(g_kv + base + (size_t)(c + 1) * cstr);
        float4 x2 = *(const float4*)(g_kv + base + (size_t)(c + 2) * cstr);
        float4 x3 = *(const float4*)(g_kv + base + (size_t)(c + 3) * cstr);
        *(float4*)(g_kvpre + base + (size_t)(c + 0) * cstr) = run;
        run.x += x0.x; run.y += x0.y; run.z += x0.z; run.w += x0.w;
        *(float4*)(g_kvpre + base + (size_t)(c + 1) * cstr) = run;
        run.x += x1.x; run.y += x1.y; run.z += x1.z; run.w += x1.w;
        *(float4*)(g_kvpre + base + (size_t)(c + 2) * cstr) = run;
        run.x += x2.x; run.y += x2.y; run.z += x2.z; run.w += x2.w;
        *(float4*)(g_kvpre + base + (size_t)(c + 3) * cstr) = run;
        run.x += x3.x; run.y += x3.y; run.z += x3.z; run.w += x3.w;
    }

    if (gid < Bc * DK) {
        const int bb = gid >> 7, kk = gid & 127;
        float r = 0.f;
#pragma unroll 4
        for (int c = 0; c < NC; c++) {
            const size_t id = (size_t)(bb * NC + c) * DK + kk;
            g_kspre[id] = r;
            r += g_ks[id];
        }
    }
}

// ---------------------------------------------------------------------------
// Kernel 3: per chunk: A = mask(phiQ phiK^T); out = (A V + phiQ Spre) / Z
// grid = TC, 512 threads. smem ~118 KB
// ---------------------------------------------------------------------------
__global__ void __launch_bounds__(512, 1)
k_output(const float* __restrict__ Q, const float* __restrict__ K,
         const float* __restrict__ V, float* __restrict__ out) {
    extern __shared__ float sm[];
    float* sQt = sm;                       // [DK][PT]  phiQ transposed
    float* sKt = sQt + DK * PT;            // [DK][PT]  phiK transposed
    float* sA  = sKt + DK * PT;            // [C][PA]   A stored [j][i]
    float* sV  = sA  + C * PA;             // [C][DV]
    float* sKs = sV  + C * DV;             // [DK]
    float* sZ  = sKs + DK;                 // [C]

    const int bc = blockIdx.x;
    const int b  = bc / NC;
    const int c  = bc % NC;
    const int l0 = c * C;
    const int tid = threadIdx.x;

    for (int e = tid; e < C * DK; e += 512) {
        const int i = e >> 7, k = e & 127;
        const size_t g = ((size_t)(b * Lc + l0 + i)) * DK + k;
        sQt[k * PT + i] = phi(Q[g]);
        sKt[k * PT + i] = phi(K[g]);
        sV[e] = V[g];
    }
    if (tid < DK) sKs[tid] = g_kspre[(size_t)bc * DK + tid];
    if (tid < C)  sZ[tid] = 0.f;
    __syncthreads();

    const int ty = tid >> 5, tx = tid & 31;
    const int i0 = ty * 4;                  // 16 warps x 4 rows = 64 rows

    // ---- phase 1: A[i][j] = phiQ_i . phiK_j, masked ----
    {
        const int j0 = tx * 2;              // 32 lanes x 2 cols = 64 cols
        u64 aA[2][2] = { {0ull, 0ull}, {0ull, 0ull} };  // [i-pair][j]
#pragma unroll 8
        for (int k = 0; k < DK; k++) {
            u64 a01 = *(const u64*)&sQt[k * PT + i0];      // rows i0,i0+1 (broadcast)
            u64 a23 = *(const u64*)&sQt[k * PT + i0 + 2];
            float b0 = sKt[k * PT + j0];
            float b1 = sKt[k * PT + j0 + 1];
            u64 br0 = pk(b0, b0), br1 = pk(b1, b1);
            fma2(aA[0][0], a01, br0); fma2(aA[0][1], a01, br1);
            fma2(aA[1][0], a23, br0); fma2(aA[1][1], a23, br1);
        }
#pragma unroll
        for (int ip = 0; ip < 2; ip++)
#pragma unroll
            for (int s = 0; s < 2; s++) {
                float2 v = up(aA[ip][s]);
                const int ia = i0 + 2 * ip, j = j0 + s;
                sA[j * PA + ia    ] = (ia     >= j) ? v.x : 0.f;
                sA[j * PA + ia + 1] = (ia + 1 >= j) ? v.y : 0.f;
            }
    }
    __syncthreads();

    // ---- Z (parallel over all 512 threads): rowsum(A) + phiQ . Kspre ----
    {
        const int iz = tid & 63, p = tid >> 6;     // 8 partials per row
        float zp = 0.f;
#pragma unroll
        for (int j = p * 8; j < p * 8 + 8; j++) zp += sA[j * PA + iz];
#pragma unroll
        for (int k = p * 16; k < p * 16 + 16; k++) zp += sQt[k * PT + iz] * sKs[k];
        atomicAdd(&sZ[iz], zp);
    }

    // ---- phase 2: out = A @ V + phiQ @ Spre ----
    const int v0 = tx * 4;                  // 32 lanes x 4 cols = 128 cols
    u64 acc[2][4];                          // [i-pair][v]
#pragma unroll
    for (int ip = 0; ip < 2; ip++)
#pragma unroll
        for (int s = 0; s < 4; s++) acc[ip][s] = 0ull;

#pragma unroll 4
    for (int j = 0; j < C; j++) {           // intra-chunk
        u64 a01 = *(const u64*)&sA[j * PA + i0];
        u64 a23 = *(const u64*)&sA[j * PA + i0 + 2];
        float4 bv = *(const float4*)&sV[j * DV + v0];
        u64 br[4] = { pk(bv.x, bv.x), pk(bv.y, bv.y), pk(bv.z, bv.z), pk(bv.w, bv.w) };
#pragma unroll
        for (int s = 0; s < 4; s++) { fma2(acc[0][s], a01, br[s]); fma2(acc[1][s], a23, br[s]); }
    }

    const float* Sp = g_kvpre + (size_t)bc * DK * DV;
#pragma unroll 4
    for (int k = 0; k < DK; k++) {          // inter-chunk (Spre is L2/L1-resident)
        u64 a01 = *(const u64*)&sQt[k * PT + i0];
        u64 a23 = *(const u64*)&sQt[k * PT + i0 + 2];
        float4 bv = __ldg((const float4*)&Sp[(size_t)k * DV + v0]);
        u64 br[4] = { pk(bv.x, bv.x), pk(bv.y, bv.y), pk(bv.z, bv.z), pk(bv.w, bv.w) };
#pragma unroll
        for (int s = 0; s < 4; s++) { fma2(acc[0][s], a01, br[s]); fma2(acc[1][s], a23, br[s]); }
    }

    __syncthreads();   // sZ atomics complete

#pragma unroll
    for (int ip = 0; ip < 2; ip++) {
        const int ia = i0 + 2 * ip;
        const float z0 = 1.f / (sZ[ia] + EPS);
        const float z1 = 1.f / (sZ[ia + 1] + EPS);
        float2 c0 = up(acc[ip][0]), c1 = up(acc[ip][1]);
        float2 c2 = up(acc[ip][2]), c3 = up(acc[ip][3]);
        const size_t g0 = ((size_t)(b * Lc + l0 + ia)) * DV + v0;
        const size_t g1 = g0 + DV;
        *(float4*)&out[g0] = make_float4(c0.x * z0, c1.x * z0, c2.x * z0, c3.x * z0);
        *(float4*)&out[g1] = make_float4(c0.y * z1, c1.y * z1, c2.y * z1, c3.y * z1);
    }
}

// ---------------------------------------------------------------------------
extern "C" void kernel_launch(void* const* d_in, const int* in_sizes, int n_in,
                              void* d_out, int out_size) {
    const float* Q = (const float*)d_in[0];
    const float* K = (const float*)d_in[1];
    const float* V = (const float*)d_in[2];
    float* out = (float*)d_out;

    const int smem1 = (C * DK + C * DV) * (int)sizeof(float);
    const int smem3 = (2 * DK * PT + C * PA + C * DV + DK + C) * (int)sizeof(float);

    cudaFuncSetAttribute(k_chunk_kv, cudaFuncAttributeMaxDynamicSharedMemorySize, smem1);
    cudaFuncSetAttribute(k_output,  cudaFuncAttributeMaxDynamicSharedMemorySize, smem3);

    k_chunk_kv<<<TC, 512, smem1>>>(K, V);
    k_scan<<<128, 64>>>();
    k_output<<<TC, 512, smem3>>>(Q, K, V, out);
}

// round 4
// speedup vs baseline: 1.6619x; 1.1245x over previous
#include <cuda_runtime.h>
#include <cuda_bf16.h>
#include <cstdint>

typedef unsigned long long u64;

constexpr int Bc = 2;
constexpr int Lc = 4096;
constexpr int DK = 128;
constexpr int DV = 128;
constexpr int C  = 64;
constexpr int NC = Lc / C;       // 64
constexpr int TC = Bc * NC;      // 128
constexpr float EPS = 1e-6f;

constexpr int PL = 66;           // l-contiguous row stride (transposed K/V)
constexpr int PK = 130;          // k-contiguous row stride (Q, K, Spre)
constexpr int PJ = 66;           // j-contiguous row stride (A)

// Scratch: g_kv / g_kvpre stored [bc][v][k] (k contiguous)
__device__ float g_kv   [(size_t)TC * DK * DV];
__device__ float g_kvpre[(size_t)TC * DK * DV];
__device__ float g_ks   [(size_t)TC * DK];
__device__ float g_kspre[(size_t)TC * DK];

__device__ __forceinline__ float phi(float x) {
    return x > 0.f ? x + 1.f : __expf(x);
}

__device__ __forceinline__ void fma2(u64& d, u64 a, u64 b) {
    asm("fma.rn.f32x2 %0, %1, %2, %0;" : "+l"(d) : "l"(a), "l"(b));
}
__device__ __forceinline__ float2 up2(u64 v) {
    float2 f; asm("mov.b64 {%0, %1}, %2;" : "=f"(f.x), "=f"(f.y) : "l"(v)); return f;
}
__device__ __forceinline__ u64 lds64(const float* p) {
    return *reinterpret_cast<const u64*>(p);
}

// ---------------------------------------------------------------------------
// Kernel 1: KV[v][k] = sum_l phiK[l][k] V[l][v];  grid = 2*TC (v halves)
// pair-packed over l. smem: sKt[128][PL] + sVt[64][PL]  (~50.7 KB)
// ---------------------------------------------------------------------------
__global__ void __launch_bounds__(512, 2)
k_chunk_kv(const float* __restrict__ K, const float* __restrict__ V) {
    extern __shared__ float sm[];
    float* sKt = sm;               // [DK][PL]  phiK transposed (l-contig)
    float* sVt = sm + DK * PL;     // [64][PL]  V-half transposed

    const int bc = blockIdx.x >> 1;
    const int vh = (blockIdx.x & 1) * 64;
    const int b  = bc / NC;
    const int c  = bc % NC;
    const int l0 = c * C;
    const int tid = threadIdx.x;

    // K transpose + phi : 2048 float4 loads
    for (int e = tid; e < 2048; e += 512) {
        const int l = e >> 5, k4 = (e & 31) * 4;
        float4 x = *(const float4*)&K[((size_t)(b * Lc + l0 + l)) * DK + k4];
        sKt[(k4 + 0) * PL + l] = phi(x.x);
        sKt[(k4 + 1) * PL + l] = phi(x.y);
        sKt[(k4 + 2) * PL + l] = phi(x.z);
        sKt[(k4 + 3) * PL + l] = phi(x.w);
    }
    // V half transpose : 1024 float4 loads
    for (int e = tid; e < 1024; e += 512) {
        const int l = e >> 4, v4 = (e & 15) * 4;
        float4 x = *(const float4*)&V[((size_t)(b * Lc + l0 + l)) * DV + vh + v4];
        sVt[(v4 + 0) * PL + l] = x.x;
        sVt[(v4 + 1) * PL + l] = x.y;
        sVt[(v4 + 2) * PL + l] = x.z;
        sVt[(v4 + 3) * PL + l] = x.w;
    }
    __syncthreads();

    const int w = tid >> 5, tx = tid & 31;
    const int half = tx >> 4, txl = tx & 15;
    const int k0 = w * 8 + half * 4;      // 4 k-rows per thread

    u64 acc[4][4];                        // [k r][v s], pair over l
#pragma unroll
    for (int r = 0; r < 4; r++)
#pragma unroll
        for (int s = 0; s < 4; s++) acc[r][s] = 0ull;

#pragma unroll
    for (int lp = 0; lp < C / 2; lp++) {
        u64 a[4], bb[4];
#pragma unroll
        for (int r = 0; r < 4; r++) a[r] = lds64(&sKt[(k0 + r) * PL + 2 * lp]);
#pragma unroll
        for (int s = 0; s < 4; s++) bb[s] = lds64(&sVt[(txl + 16 * s) * PL + 2 * lp]);
#pragma unroll
        for (int r = 0; r < 4; r++)
#pragma unroll
            for (int s = 0; s < 4; s++) fma2(acc[r][s], a[r], bb[s]);
    }

    // store g_kv[bc][v][k] : per s one float4 over the 4 k's (DK stride -> aligned)
    float* kvout = g_kv + (size_t)bc * DK * DV;
#pragma unroll
    for (int s = 0; s < 4; s++) {
        const int v = vh + txl + 16 * s;
        float2 e0 = up2(acc[0][s]), e1 = up2(acc[1][s]);
        float2 e2 = up2(acc[2][s]), e3 = up2(acc[3][s]);
        *(float4*)&kvout[(size_t)v * DK + k0] =
            make_float4(e0.x + e0.y, e1.x + e1.y, e2.x + e2.y, e3.x + e3.y);
    }

    // per-chunk phiK column sums (only v-half 0 writes)
    if (vh == 0 && tid < DK) {
        const float* row = &sKt[tid * PL];
        float s = 0.f;
#pragma unroll
        for (int l = 0; l < C; l += 2) { float2 t = *(const float2*)&row[l]; s += t.x + t.y; }
        g_ks[(size_t)bc * DK + tid] = s;
    }
}

// ---------------------------------------------------------------------------
// Kernel 2: warp-parallel exclusive scan over chunks (lane = chunk)
// 8192 kv-warps + 64 ks-warps = 8256 warps -> 516 CTAs x 512
// ---------------------------------------------------------------------------
__device__ __forceinline__ float warp_excl_scan(float x, int lane) {
#pragma unroll
    for (int d = 1; d < 32; d <<= 1) {
        float t = __shfl_up_sync(0xffffffffu, x, d);
        if (lane >= d) x += t;
    }
    float e = __shfl_up_sync(0xffffffffu, x, 1);
    return lane == 0 ? 0.f : e;
}

__global__ void __launch_bounds__(512, 2)
k_scan(void) {
    const int gw = blockIdx.x * 16 + (threadIdx.x >> 5);
    const int lane = threadIdx.x & 31;
    if (gw < 8192) {
        // warp scans NC=64 chunks as two 32-wide passes with carry
        const int b   = gw >> 12;
        const int rem = gw & 4095;
        const int v   = rem >> 5;
        const int k4  = (rem & 31) * 4;
        const size_t cstr = (size_t)DK * DV;
        const size_t base = (size_t)(b * NC) * cstr + (size_t)v * DK + k4;

        float4 carry = make_float4(0.f, 0.f, 0.f, 0.f);
#pragma unroll
        for (int pass = 0; pass < 2; pass++) {
            const size_t idx = base + (size_t)(pass * 32 + lane) * cstr;
            float4 x = *(const float4*)(g_kv + idx);
            float4 ex;
            ex.x = warp_excl_scan(x.x, lane) + carry.x;
            ex.y = warp_excl_scan(x.y, lane) + carry.y;
            ex.z = warp_excl_scan(x.z, lane) + carry.z;
            ex.w = warp_excl_scan(x.w, lane) + carry.w;
            *(float4*)(g_kvpre + idx) = ex;
            carry.x = __shfl_sync(0xffffffffu, ex.x + x.x, 31);
            carry.y = __shfl_sync(0xffffffffu, ex.y + x.y, 31);
            carry.z = __shfl_sync(0xffffffffu, ex.z + x.z, 31);
            carry.w = __shfl_sync(0xffffffffu, ex.w + x.w, 31);
        }
    } else if (gw < 8192 + 64) {
        const int t  = gw - 8192;
        const int b  = t >> 5;
        const int k4 = (t & 31) * 4;
        const size_t base = (size_t)(b * NC) * DK + k4;
        float4 carry = make_float4(0.f, 0.f, 0.f, 0.f);
#pragma unroll
        for (int pass = 0; pass < 2; pass++) {
            const size_t idx = base + (size_t)(pass * 32 + lane) * DK;
            float4 x = *(const float4*)(g_ks + idx);
            float4 ex;
            ex.x = warp_excl_scan(x.x, lane) + carry.x;
            ex.y = warp_excl_scan(x.y, lane) + carry.y;
            ex.z = warp_excl_scan(x.z, lane) + carry.z;
            ex.w = warp_excl_scan(x.w, lane) + carry.w;
            *(float4*)(g_kspre + idx) = ex;
            carry.x = __shfl_sync(0xffffffffu, ex.x + x.x, 31);
            carry.y = __shfl_sync(0xffffffffu, ex.y + x.y, 31);
            carry.z = __shfl_sync(0xffffffffu, ex.z + x.z, 31);
            carry.w = __shfl_sync(0xffffffffu, ex.w + x.w, 31);
        }
    }
}

// ---------------------------------------------------------------------------
// Kernel 3: A = mask(phiQ phiK^T); out = (A V + phiQ Spre) / Z
// all GEMMs pair-packed over the reduction dim. smem ~184.6 KB
// ---------------------------------------------------------------------------
__global__ void __launch_bounds__(512, 1)
k_output(const float* __restrict__ Q, const float* __restrict__ K,
         const float* __restrict__ V, float* __restrict__ out) {
    extern __shared__ float sm[];
    float* sQ  = sm;                        // [64][PK] phiQ row-major (k contig)
    float* sK  = sQ  + C * PK;              // [64][PK] phiK row-major
    float* sA  = sK  + C * PK;              // [64][PJ] A row-major (j contig)
    float* sVt = sA  + C * PJ;              // [128][PL] V transposed (l contig)
    float* sSt = sVt + DV * PL;             // [128][PK] Spre [v][k] (k contig)
    float* sKs = sSt + DV * PK;             // [128]
    float* sZ  = sKs + DK;                  // [64]

    const int bc = blockIdx.x;
    const int b  = bc / NC;
    const int c  = bc % NC;
    const int l0 = c * C;
    const int tid = threadIdx.x;

    // Q, K row-major with phi (coalesced loads; 8B-aligned float2 stores)
    for (int e = tid; e < 2048; e += 512) {
        const int l = e >> 5, k4 = (e & 31) * 4;
        const size_t g = ((size_t)(b * Lc + l0 + l)) * DK + k4;
        float4 q = *(const float4*)&Q[g];
        float4 k = *(const float4*)&K[g];
        *(float2*)&sQ[l * PK + k4]     = make_float2(phi(q.x), phi(q.y));
        *(float2*)&sQ[l * PK + k4 + 2] = make_float2(phi(q.z), phi(q.w));
        *(float2*)&sK[l * PK + k4]     = make_float2(phi(k.x), phi(k.y));
        *(float2*)&sK[l * PK + k4 + 2] = make_float2(phi(k.z), phi(k.w));
    }
    // V transpose
    for (int e = tid; e < 2048; e += 512) {
        const int l = e >> 5, v4 = (e & 31) * 4;
        float4 x = *(const float4*)&V[((size_t)(b * Lc + l0 + l)) * DV + v4];
        sVt[(v4 + 0) * PL + l] = x.x;
        sVt[(v4 + 1) * PL + l] = x.y;
        sVt[(v4 + 2) * PL + l] = x.z;
        sVt[(v4 + 3) * PL + l] = x.w;
    }
    // stage Spre [v][k]: float4 gmem load, float2 smem stores (PK=130 -> only 8B aligned)
    {
        const float* Sp = g_kvpre + (size_t)bc * DK * DV;
        for (int e = tid; e < 4096; e += 512) {
            const int v = e >> 5, k4 = (e & 31) * 4;
            float4 x = *(const float4*)&Sp[(size_t)v * DK + k4];
            *(float2*)&sSt[v * PK + k4]     = make_float2(x.x, x.y);
            *(float2*)&sSt[v * PK + k4 + 2] = make_float2(x.z, x.w);
        }
    }
    if (tid < DK) sKs[tid] = g_kspre[(size_t)bc * DK + tid];
    if (tid < C)  sZ[tid] = 0.f;
    __syncthreads();

    const int w = tid >> 5, tx = tid & 31;
    const int half = tx >> 4, txl = tx & 15;

    // ---- phase 1: A (pair over k). thread: 2 i x 4 j ----
    {
        const int i0 = w * 4 + half * 2;
        u64 aA[2][4];
#pragma unroll
        for (int r = 0; r < 2; r++)
#pragma unroll
            for (int s = 0; s < 4; s++) aA[r][s] = 0ull;

#pragma unroll
        for (int kp = 0; kp < DK / 2; kp++) {
            u64 a0 = lds64(&sQ[(i0    ) * PK + 2 * kp]);
            u64 a1 = lds64(&sQ[(i0 + 1) * PK + 2 * kp]);
            u64 bb[4];
#pragma unroll
            for (int s = 0; s < 4; s++) bb[s] = lds64(&sK[(txl + 16 * s) * PK + 2 * kp]);
#pragma unroll
            for (int s = 0; s < 4; s++) { fma2(aA[0][s], a0, bb[s]); fma2(aA[1][s], a1, bb[s]); }
        }
#pragma unroll
        for (int r = 0; r < 2; r++)
#pragma unroll
            for (int s = 0; s < 4; s++) {
                const int i = i0 + r, j = txl + 16 * s;
                float2 v = up2(aA[r][s]);
                sA[i * PJ + j] = (i >= j) ? (v.x + v.y) : 0.f;
            }
    }
    __syncthreads();

    // ---- Z: rowsum(A) + phiQ . Kspre (8 partials per row) ----
    {
        const int iz = tid & 63, p = tid >> 6;
        float zp = 0.f;
#pragma unroll
        for (int j = p * 8; j < p * 8 + 8; j++) zp += sA[iz * PJ + j];
#pragma unroll
        for (int k = p * 16; k < p * 16 + 16; k++) zp += sQ[iz * PK + k] * sKs[k];
        atomicAdd(&sZ[iz], zp);
    }

    // ---- phase 2: out = A V + phiQ Spre (pair over j / k). thread: 4 i x 4 v ----
    const int i0 = (w & 7) * 8 + half * 4;
    const int vg = (w >> 3) * 64;
    u64 acc[4][4];
#pragma unroll
    for (int r = 0; r < 4; r++)
#pragma unroll
        for (int s = 0; s < 4; s++) acc[r][s] = 0ull;

#pragma unroll
    for (int jp = 0; jp < C / 2; jp++) {          // intra-chunk
        u64 a[4], bb[4];
#pragma unroll
        for (int r = 0; r < 4; r++) a[r] = lds64(&sA[(i0 + r) * PJ + 2 * jp]);
#pragma unroll
        for (int s = 0; s < 4; s++) bb[s] = lds64(&sVt[(vg + txl + 16 * s) * PL + 2 * jp]);
#pragma unroll
        for (int r = 0; r < 4; r++)
#pragma unroll
            for (int s = 0; s < 4; s++) fma2(acc[r][s], a[r], bb[s]);
    }
#pragma unroll
    for (int kp = 0; kp < DK / 2; kp++) {         // inter-chunk
        u64 a[4], bb[4];
#pragma unroll
        for (int r = 0; r < 4; r++) a[r] = lds64(&sQ[(i0 + r) * PK + 2 * kp]);
#pragma unroll
        for (int s = 0; s < 4; s++) bb[s] = lds64(&sSt[(vg + txl + 16 * s) * PK + 2 * kp]);
#pragma unroll
        for (int r = 0; r < 4; r++)
#pragma unroll
            for (int s = 0; s < 4; s++) fma2(acc[r][s], a[r], bb[s]);
    }

    __syncthreads();   // sZ complete

#pragma unroll
    for (int r = 0; r < 4; r++) {
        const int i = i0 + r;
        const float invz = 1.f / (sZ[i] + EPS);
        const size_t g = ((size_t)(b * Lc + l0 + i)) * DV;
#pragma unroll
        for (int s = 0; s < 4; s++) {
            float2 v = up2(acc[r][s]);
            out[g + vg + txl + 16 * s] = (v.x + v.y) * invz;
        }
    }
}

// ---------------------------------------------------------------------------
extern "C" void kernel_launch(void* const* d_in, const int* in_sizes, int n_in,
                              void* d_out, int out_size) {
    const float* Q = (const float*)d_in[0];
    const float* K = (const float*)d_in[1];
    const float* V = (const float*)d_in[2];
    float* out = (float*)d_out;

    const int smem1 = (DK * PL + 64 * PL) * (int)sizeof(float);                  // ~50.7 KB
    const int smem3 = (2 * C * PK + C * PJ + DV * PL + DV * PK + DK + C)
                      * (int)sizeof(float);                                      // ~184.6 KB

    cudaFuncSetAttribute(k_chunk_kv, cudaFuncAttributeMaxDynamicSharedMemorySize, smem1);
    cudaFuncSetAttribute(k_output,  cudaFuncAttributeMaxDynamicSharedMemorySize, smem3);

    k_chunk_kv<<<2 * TC, 512, smem1>>>(K, V);
    k_scan<<<516, 512>>>();
    k_output<<<TC, 512, smem3>>>(Q, K, V, out);
}

// round 5
// speedup vs baseline: 1.8090x; 1.0885x over previous
#include <cuda_runtime.h>
#include <cuda_bf16.h>
#include <cstdint>

typedef unsigned long long u64;

constexpr int Bc = 2;
constexpr int Lc = 4096;
constexpr int DK = 128;
constexpr int DV = 128;
constexpr int C  = 64;
constexpr int NC = Lc / C;       // 64
constexpr int TC = Bc * NC;      // 128
constexpr float EPS = 1e-6f;

constexpr int PL = 66;           // l-contiguous row stride (transposed K/V)
constexpr int PK = 130;          // k-contiguous row stride (Q, K, Spre)
constexpr int PJ = 66;           // j-contiguous row stride (A)

// Scratch: g_kv / g_kvpre stored [bc][v][k] (k contiguous)
__device__ float g_kv   [(size_t)TC * DK * DV];
__device__ float g_kvpre[(size_t)TC * DK * DV];
__device__ float g_ks   [(size_t)TC * DK];
__device__ float g_kspre[(size_t)TC * DK];

__device__ __forceinline__ float phi(float x) {
    return x > 0.f ? x + 1.f : __expf(x);
}

__device__ __forceinline__ void fma2(u64& d, u64 a, u64 b) {
    asm("fma.rn.f32x2 %0, %1, %2, %0;" : "+l"(d) : "l"(a), "l"(b));
}
__device__ __forceinline__ float2 up2(u64 v) {
    float2 f; asm("mov.b64 {%0, %1}, %2;" : "=f"(f.x), "=f"(f.y) : "l"(v)); return f;
}
__device__ __forceinline__ u64 lds64(const float* p) {
    return *reinterpret_cast<const u64*>(p);
}

// ---------------------------------------------------------------------------
// Kernel 1: KV[v][k] = sum_l phiK[l][k] V[l][v];  grid = 2*TC (v halves)
// pair-packed over l. smem: sKt[128][PL] + sVt[64][PL]  (~50.7 KB)
// ---------------------------------------------------------------------------
__global__ void __launch_bounds__(512, 2)
k_chunk_kv(const float* __restrict__ K, const float* __restrict__ V) {
    extern __shared__ float sm[];
    float* sKt = sm;               // [DK][PL]  phiK transposed (l-contig)
    float* sVt = sm + DK * PL;     // [64][PL]  V-half transposed

    const int bc = blockIdx.x >> 1;
    const int vh = (blockIdx.x & 1) * 64;
    const int b  = bc / NC;
    const int c  = bc % NC;
    const int l0 = c * C;
    const int tid = threadIdx.x;

    // K transpose + phi. lane -> k (coalesced 4B), k strided by 32.
    // STS lane-stride = PL mod 32 = 2 -> 2-way conflict only.
    for (int e = tid; e < 2048; e += 512) {
        const int l = e >> 5, kb = e & 31;
        const float* src = &K[((size_t)(b * Lc + l0 + l)) * DK + kb];
        float* dst = &sKt[kb * PL + l];
#pragma unroll
        for (int j = 0; j < 4; j++)
            dst[j * 32 * PL] = phi(src[j * 32]);
    }
    // V half transpose, same pattern (64 v-cols -> 2 strided groups)
    for (int e = tid; e < 2048; e += 512) {
        const int l = e >> 5, vb = e & 31;
        const float* src = &V[((size_t)(b * Lc + l0 + l)) * DV + vh + vb];
        float* dst = &sVt[vb * PL + l];
#pragma unroll
        for (int j = 0; j < 2; j++)
            dst[j * 32 * PL] = src[j * 32];
    }
    __syncthreads();

    const int w = tid >> 5, tx = tid & 31;
    const int half = tx >> 4, txl = tx & 15;
    const int k0 = w * 8 + half * 4;      // 4 k-rows per thread

    u64 acc[4][4];                        // [k r][v s], pair over l
#pragma unroll
    for (int r = 0; r < 4; r++)
#pragma unroll
        for (int s = 0; s < 4; s++) acc[r][s] = 0ull;

#pragma unroll
    for (int lp = 0; lp < C / 2; lp++) {
        u64 a[4], bb[4];
#pragma unroll
        for (int r = 0; r < 4; r++) a[r] = lds64(&sKt[(k0 + r) * PL + 2 * lp]);
#pragma unroll
        for (int s = 0; s < 4; s++) bb[s] = lds64(&sVt[(txl + 16 * s) * PL + 2 * lp]);
#pragma unroll
        for (int r = 0; r < 4; r++)
#pragma unroll
            for (int s = 0; s < 4; s++) fma2(acc[r][s], a[r], bb[s]);
    }

    // store g_kv[bc][v][k] : per s one float4 over the 4 k's (DK stride -> aligned)
    float* kvout = g_kv + (size_t)bc * DK * DV;
#pragma unroll
    for (int s = 0; s < 4; s++) {
        const int v = vh + txl + 16 * s;
        float2 e0 = up2(acc[0][s]), e1 = up2(acc[1][s]);
        float2 e2 = up2(acc[2][s]), e3 = up2(acc[3][s]);
        *(float4*)&kvout[(size_t)v * DK + k0] =
            make_float4(e0.x + e0.y, e1.x + e1.y, e2.x + e2.y, e3.x + e3.y);
    }

    // per-chunk phiK column sums (only v-half 0 writes)
    if (vh == 0 && tid < DK) {
        const float* row = &sKt[tid * PL];
        float s = 0.f;
#pragma unroll
        for (int l = 0; l < C; l += 2) { float2 t = *(const float2*)&row[l]; s += t.x + t.y; }
        g_ks[(size_t)bc * DK + tid] = s;
    }
}

// ---------------------------------------------------------------------------
// Kernel 2: warp-parallel exclusive scan over chunks
// ---------------------------------------------------------------------------
__device__ __forceinline__ float warp_excl_scan(float x, int lane) {
#pragma unroll
    for (int d = 1; d < 32; d <<= 1) {
        float t = __shfl_up_sync(0xffffffffu, x, d);
        if (lane >= d) x += t;
    }
    float e = __shfl_up_sync(0xffffffffu, x, 1);
    return lane == 0 ? 0.f : e;
}

__global__ void __launch_bounds__(512, 2)
k_scan(void) {
    const int gw = blockIdx.x * 16 + (threadIdx.x >> 5);
    const int lane = threadIdx.x & 31;
    if (gw < 8192) {
        const int b   = gw >> 12;
        const int rem = gw & 4095;
        const int v   = rem >> 5;
        const int k4  = (rem & 31) * 4;
        const size_t cstr = (size_t)DK * DV;
        const size_t base = (size_t)(b * NC) * cstr + (size_t)v * DK + k4;

        float4 carry = make_float4(0.f, 0.f, 0.f, 0.f);
#pragma unroll
        for (int pass = 0; pass < 2; pass++) {
            const size_t idx = base + (size_t)(pass * 32 + lane) * cstr;
            float4 x = *(const float4*)(g_kv + idx);
            float4 ex;
            ex.x = warp_excl_scan(x.x, lane) + carry.x;
            ex.y = warp_excl_scan(x.y, lane) + carry.y;
            ex.z = warp_excl_scan(x.z, lane) + carry.z;
            ex.w = warp_excl_scan(x.w, lane) + carry.w;
            *(float4*)(g_kvpre + idx) = ex;
            carry.x = __shfl_sync(0xffffffffu, ex.x + x.x, 31);
            carry.y = __shfl_sync(0xffffffffu, ex.y + x.y, 31);
            carry.z = __shfl_sync(0xffffffffu, ex.z + x.z, 31);
            carry.w = __shfl_sync(0xffffffffu, ex.w + x.w, 31);
        }
    } else if (gw < 8192 + 64) {
        const int t  = gw - 8192;
        const int b  = t >> 5;
        const int k4 = (t & 31) * 4;
        const size_t base = (size_t)(b * NC) * DK + k4;
        float4 carry = make_float4(0.f, 0.f, 0.f, 0.f);
#pragma unroll
        for (int pass = 0; pass < 2; pass++) {
            const size_t idx = base + (size_t)(pass * 32 + lane) * DK;
            float4 x = *(const float4*)(g_ks + idx);
            float4 ex;
            ex.x = warp_excl_scan(x.x, lane) + carry.x;
            ex.y = warp_excl_scan(x.y, lane) + carry.y;
            ex.z = warp_excl_scan(x.z, lane) + carry.z;
            ex.w = warp_excl_scan(x.w, lane) + carry.w;
            *(float4*)(g_kspre + idx) = ex;
            carry.x = __shfl_sync(0xffffffffu, ex.x + x.x, 31);
            carry.y = __shfl_sync(0xffffffffu, ex.y + x.y, 31);
            carry.z = __shfl_sync(0xffffffffu, ex.z + x.z, 31);
            carry.w = __shfl_sync(0xffffffffu, ex.w + x.w, 31);
        }
    }
}

// ---------------------------------------------------------------------------
// Kernel 3: A = mask(phiQ phiK^T); out = (A V + phiQ Spre) / Z
// ---------------------------------------------------------------------------
__global__ void __launch_bounds__(512, 1)
k_output(const float* __restrict__ Q, const float* __restrict__ K,
         const float* __restrict__ V, float* __restrict__ out) {
    extern __shared__ float sm[];
    float* sQ  = sm;                        // [64][PK] phiQ row-major (k contig)
    float* sK  = sQ  + C * PK;              // [64][PK] phiK row-major
    float* sA  = sK  + C * PK;              // [64][PJ] A row-major (j contig)
    float* sVt = sA  + C * PJ;              // [128][PL] V transposed (l contig)
    float* sSt = sVt + DV * PL;             // [128][PK] Spre [v][k] (k contig)
    float* sKs = sSt + DV * PK;             // [128]
    float* sZ  = sKs + DK;                  // [64]

    const int bc = blockIdx.x;
    const int b  = bc / NC;
    const int c  = bc % NC;
    const int l0 = c * C;
    const int tid = threadIdx.x;

    // Q, K row-major with phi. lane -> k, strided by 32: coalesced loads,
    // conflict-free STS (lane-stride 1).
    for (int e = tid; e < 2048; e += 512) {
        const int l = e >> 5, kb = e & 31;
        const size_t g = ((size_t)(b * Lc + l0 + l)) * DK + kb;
        float* dq = &sQ[l * PK + kb];
        float* dk = &sK[l * PK + kb];
#pragma unroll
        for (int j = 0; j < 4; j++) {
            dq[j * 32] = phi(Q[g + j * 32]);
            dk[j * 32] = phi(K[g + j * 32]);
        }
    }
    // V transpose: 2-way STS conflicts only
    for (int e = tid; e < 2048; e += 512) {
        const int l = e >> 5, vb = e & 31;
        const float* src = &V[((size_t)(b * Lc + l0 + l)) * DV + vb];
        float* dst = &sVt[vb * PL + l];
#pragma unroll
        for (int j = 0; j < 4; j++)
            dst[j * 32 * PL] = src[j * 32];
    }
    // stage Spre [v][k]: coalesced loads, conflict-free STS
    {
        const float* Sp = g_kvpre + (size_t)bc * DK * DV;
        for (int e = tid; e < 4096; e += 512) {
            const int v = e >> 5, kb = e & 31;
            const float* src = &Sp[(size_t)v * DK + kb];
            float* dst = &sSt[v * PK + kb];
#pragma unroll
            for (int j = 0; j < 4; j++)
                dst[j * 32] = src[j * 32];
        }
    }
    if (tid < DK) sKs[tid] = g_kspre[(size_t)bc * DK + tid];
    if (tid < C)  sZ[tid] = 0.f;
    __syncthreads();

    const int w = tid >> 5, tx = tid & 31;
    const int half = tx >> 4, txl = tx & 15;

    // ---- phase 1: A (pair over k). thread: 2 i x 4 j ----
    {
        const int i0 = w * 4 + half * 2;
        u64 aA[2][4];
#pragma unroll
        for (int r = 0; r < 2; r++)
#pragma unroll
            for (int s = 0; s < 4; s++) aA[r][s] = 0ull;

#pragma unroll
        for (int kp = 0; kp < DK / 2; kp++) {
            u64 a0 = lds64(&sQ[(i0    ) * PK + 2 * kp]);
            u64 a1 = lds64(&sQ[(i0 + 1) * PK + 2 * kp]);
            u64 bb[4];
#pragma unroll
            for (int s = 0; s < 4; s++) bb[s] = lds64(&sK[(txl + 16 * s) * PK + 2 * kp]);
#pragma unroll
            for (int s = 0; s < 4; s++) { fma2(aA[0][s], a0, bb[s]); fma2(aA[1][s], a1, bb[s]); }
        }
#pragma unroll
        for (int r = 0; r < 2; r++)
#pragma unroll
            for (int s = 0; s < 4; s++) {
                const int i = i0 + r, j = txl + 16 * s;
                float2 v = up2(aA[r][s]);
                sA[i * PJ + j] = (i >= j) ? (v.x + v.y) : 0.f;
            }
    }
    __syncthreads();

    // ---- Z: rowsum(A) + phiQ . Kspre (8 partials per row) ----
    {
        const int iz = tid & 63, p = tid >> 6;
        float zp = 0.f;
#pragma unroll
        for (int j = p * 8; j < p * 8 + 8; j++) zp += sA[iz * PJ + j];
#pragma unroll
        for (int k = p * 16; k < p * 16 + 16; k++) zp += sQ[iz * PK + k] * sKs[k];
        atomicAdd(&sZ[iz], zp);
    }

    // ---- phase 2: out = A V + phiQ Spre (pair over j / k). thread: 4 i x 4 v ----
    const int i0 = (w & 7) * 8 + half * 4;
    const int vg = (w >> 3) * 64;
    u64 acc[4][4];
#pragma unroll
    for (int r = 0; r < 4; r++)
#pragma unroll
        for (int s = 0; s < 4; s++) acc[r][s] = 0ull;

#pragma unroll
    for (int jp = 0; jp < C / 2; jp++) {          // intra-chunk
        u64 a[4], bb[4];
#pragma unroll
        for (int r = 0; r < 4; r++) a[r] = lds64(&sA[(i0 + r) * PJ + 2 * jp]);
#pragma unroll
        for (int s = 0; s < 4; s++) bb[s] = lds64(&sVt[(vg + txl + 16 * s) * PL + 2 * jp]);
#pragma unroll
        for (int r = 0; r < 4; r++)
#pragma unroll
            for (int s = 0; s < 4; s++) fma2(acc[r][s], a[r], bb[s]);
    }
#pragma unroll
    for (int kp = 0; kp < DK / 2; kp++) {         // inter-chunk
        u64 a[4], bb[4];
#pragma unroll
        for (int r = 0; r < 4; r++) a[r] = lds64(&sQ[(i0 + r) * PK + 2 * kp]);
#pragma unroll
        for (int s = 0; s < 4; s++) bb[s] = lds64(&sSt[(vg + txl + 16 * s) * PK + 2 * kp]);
#pragma unroll
        for (int r = 0; r < 4; r++)
#pragma unroll
            for (int s = 0; s < 4; s++) fma2(acc[r][s], a[r], bb[s]);
    }

    __syncthreads();   // sZ complete

#pragma unroll
    for (int r = 0; r < 4; r++) {
        const int i = i0 + r;
        const float invz = 1.f / (sZ[i] + EPS);
        const size_t g = ((size_t)(b * Lc + l0 + i)) * DV;
#pragma unroll
        for (int s = 0; s < 4; s++) {
            float2 v = up2(acc[r][s]);
            out[g + vg + txl + 16 * s] = (v.x + v.y) * invz;
        }
    }
}

// ---------------------------------------------------------------------------
extern "C" void kernel_launch(void* const* d_in, const int* in_sizes, int n_in,
                              void* d_out, int out_size) {
    const float* Q = (const float*)d_in[0];
    const float* K = (const float*)d_in[1];
    const float* V = (const float*)d_in[2];
    float* out = (float*)d_out;

    const int smem1 = (DK * PL + 64 * PL) * (int)sizeof(float);                  // ~50.7 KB
    const int smem3 = (2 * C * PK + C * PJ + DV * PL + DV * PK + DK + C)
                      * (int)sizeof(float);                                      // ~184.6 KB

    cudaFuncSetAttribute(k_chunk_kv, cudaFuncAttributeMaxDynamicSharedMemorySize, smem1);
    cudaFuncSetAttribute(k_output,  cudaFuncAttributeMaxDynamicSharedMemorySize, smem3);

    k_chunk_kv<<<2 * TC, 512, smem1>>>(K, V);
    k_scan<<<516, 512>>>();
    k_output<<<TC, 512, smem3>>>(Q, K, V, out);
}